// round 6
// baseline (speedup 1.0000x reference)
#include <cuda_runtime.h>
#include <cstdint>

// Problem constants
#define BB 8
#define HH 128
#define WW 128
#define CC 16
#define HID 256
#define NL 3
#define STEPS 16
#define NELEM (BB*HH*WW*CC)   // 2,097,152

// SMEM layout (floats). CTA tile: 8 rows (y) x 16 cols (x) = 128 cells (M=128).
#define OFF_HALO 0            // channel-major halo: 16ch * 10y * 18x = 2880
#define OFF_CW   2880         // transposed conv w: [ci*9+rs][16 o] = 2304
#define OFF_P    5184         // P frags: 8mt * 2kt * 32 * 4 = 2048
#define OFF_ACT  7232         // acts (frag layout): 8mt * 32kt * 32 * 4 = 32768
#define OFF_WBUF 40000        // 2 * 8192 double-buffered weight panel
#define SMEM_FLOATS 56384
#define SMEM_BYTES (SMEM_FLOATS*4)   // 225,536 B

// Pre-swizzled weights in gmem (written once per launch)
#define WSWZ_FIRST 196608     // interim: 24 panels * 8192
#define WSWZ_LAST  200704
__device__ float g_wswz[204800];

__device__ __forceinline__ float tf32r(float x) {
    uint32_t u;
    asm("cvt.rna.tf32.f32 %0, %1;" : "=r"(u) : "f"(x));
    return __uint_as_float(u);
}

__device__ __forceinline__ void mma8(float* c, const float4& a, float b0, float b1) {
    asm volatile(
        "mma.sync.aligned.m16n8k8.row.col.f32.tf32.tf32.f32 "
        "{%0,%1,%2,%3}, {%4,%5,%6,%7}, {%8,%9}, {%0,%1,%2,%3};\n"
        : "+f"(c[0]), "+f"(c[1]), "+f"(c[2]), "+f"(c[3])
        : "r"(__float_as_uint(a.x)), "r"(__float_as_uint(a.y)),
          "r"(__float_as_uint(a.z)), "r"(__float_as_uint(a.w)),
          "r"(__float_as_uint(b0)),  "r"(__float_as_uint(b1)));
}

__device__ __forceinline__ void cpa16(uint32_t dst, const float* src) {
    asm volatile("cp.async.cg.shared.global [%0], [%1], 16;\n" :: "r"(dst), "l"(src));
}
__device__ __forceinline__ void cpa_commit() { asm volatile("cp.async.commit_group;\n" ::: "memory"); }
__device__ __forceinline__ void cpa_wait0()  { asm volatile("cp.async.wait_group 0;\n"  ::: "memory"); }

// ---------------- Pre-swizzle weights into mma fragment order (tf32) -------------
// interim: idx = ((((l*8+p)*32+nt)*2+kp)*32+lane)*4 + slot
//   value = W_l[n][k], n = nt*8+g, k = p*32 + kp*16 + t + 4*(slot&1) + 8*(slot>>1)
// first:   idx = WSWZ_FIRST + ((nt*32+lane)*4 + slot), k over 16
// last:    idx = WSWZ_LAST  + ((((p*2+ntl)*2+kp)*32+lane)*4 + slot)
__global__ void preswizzle_kernel(const float* __restrict__ wi,
                                  const float* __restrict__ wf,
                                  const float* __restrict__ wl)
{
    int idx = blockIdx.x * blockDim.x + threadIdx.x;
    if (idx >= 204800) return;
    if (idx < WSWZ_FIRST) {
        int slot = idx & 3, lane = (idx >> 2) & 31, kp = (idx >> 7) & 1;
        int nt = (idx >> 8) & 31, p = (idx >> 13) & 7, l = idx >> 16;
        int g = lane >> 2, t = lane & 3;
        int n = nt * 8 + g;
        int k = p * 32 + kp * 16 + t + 4 * (slot & 1) + 8 * (slot >> 1);
        g_wswz[idx] = tf32r(wi[(l * HID + n) * HID + k]);
    } else if (idx < WSWZ_LAST) {
        int j = idx - WSWZ_FIRST;
        int slot = j & 3, lane = (j >> 2) & 31, nt = (j >> 7) & 31;
        int g = lane >> 2, t = lane & 3;
        int n = nt * 8 + g;
        int k = t + 4 * (slot & 1) + 8 * (slot >> 1);
        g_wswz[idx] = tf32r(wf[n * CC + k]);
    } else {
        int j = idx - WSWZ_LAST;
        int slot = j & 3, lane = (j >> 2) & 31, kp = (j >> 7) & 1;
        int ntl = (j >> 8) & 1, p = (j >> 9) & 7;
        int g = lane >> 2, t = lane & 3;
        int n = ntl * 8 + g;
        int k = p * 32 + kp * 16 + t + 4 * (slot & 1) + 8 * (slot >> 1);
        g_wswz[idx] = tf32r(wl[n * HID + k]);
    }
}

// ---------------- Fused NCA step: M=128 cells per CTA, 256 threads ----------------
__global__ __launch_bounds__(256, 1)
void nca_step_kernel(const float* __restrict__ hin, float* __restrict__ hout,
                     const float* __restrict__ conv_w,
                     const float* __restrict__ b_first,
                     const float* __restrict__ b_interim)
{
    extern __shared__ float sm[];
    float* smHalo = sm + OFF_HALO;
    float* smCwT  = sm + OFF_CW;
    float* smP    = sm + OFF_P;
    float* smAct  = sm + OFF_ACT;
    float* smWbuf = sm + OFF_WBUF;
    const uint32_t smWbuf_u = (uint32_t)__cvta_generic_to_shared(smWbuf);

    const int tid  = threadIdx.x;
    const int lane = tid & 31;
    const int wid  = tid >> 5;
    const int g = lane >> 2;
    const int t = lane & 3;
    const int mw  = wid & 1;        // warp m-half: 4 m16-tiles each (M=128)
    const int n0q = wid >> 1;       // warp n-quarter: 8 n8-tiles each (N=256)

    const int x0 = blockIdx.x * 16;
    const int y0 = blockIdx.y * 8;
    const int b  = blockIdx.z;
    const float* hbase = hin + (size_t)b * HH * WW * CC;

    // ---- Prologue prefetch: interim panel 0 -> buf0; w_first -> buf1 ----
    #pragma unroll
    for (int i = 0; i < 8; i++)
        cpa16(smWbuf_u + tid * 128 + i * 16, g_wswz + tid * 32 + i * 4);
    cpa_commit();
    #pragma unroll
    for (int i = 0; i < 4; i++)
        cpa16(smWbuf_u + 8192 * 4 + tid * 64 + i * 16, g_wswz + WSWZ_FIRST + tid * 16 + i * 4);
    cpa_commit();

    // ---- Halo (channel-major [c][y 10][x 18], zero padded) ----
    for (int f = tid; f < 2880; f += 256) {
        int xx = f % 18;
        int yy = (f / 18) % 10;
        int c  = f / 180;
        int gx = x0 - 1 + xx;
        int gy = y0 - 1 + yy;
        float v = 0.f;
        if (gy >= 0 && gy < HH && gx >= 0 && gx < WW)
            v = hbase[((size_t)gy * WW + gx) * CC + c];
        smHalo[f] = v;
    }
    // conv weights transposed: smCwT[(ci*9+rs)*16 + o]
    for (int f = tid; f < 2304; f += 256)
        smCwT[f] = conv_w[(f & 15) * 144 + (f >> 4)];
    __syncthreads();

    // ---- Conv 3x3 (fp32): thread = (cell m = tid&127, channel group og = tid>>7) ----
    {
        const int m  = tid & 127;
        const int og = tid >> 7;          // 8 output channels per thread
        const int ly = m >> 4, lx = m & 15;
        float a8[8] = {0.f,0.f,0.f,0.f,0.f,0.f,0.f,0.f};
        #pragma unroll
        for (int ci = 0; ci < 16; ci++) {
            #pragma unroll
            for (int r = 0; r < 3; r++) {
                #pragma unroll
                for (int s = 0; s < 3; s++) {
                    float hv = smHalo[ci * 180 + (ly + s) * 18 + (lx + r)];
                    const float* wp = smCwT + (ci * 9 + r * 3 + s) * 16 + og * 8;
                    float4 w0 = *(const float4*)(wp);
                    float4 w1 = *(const float4*)(wp + 4);
                    a8[0] = fmaf(hv, w0.x, a8[0]); a8[1] = fmaf(hv, w0.y, a8[1]);
                    a8[2] = fmaf(hv, w0.z, a8[2]); a8[3] = fmaf(hv, w0.w, a8[3]);
                    a8[4] = fmaf(hv, w1.x, a8[4]); a8[5] = fmaf(hv, w1.y, a8[5]);
                    a8[6] = fmaf(hv, w1.z, a8[6]); a8[7] = fmaf(hv, w1.w, a8[7]);
                }
            }
        }
        // scatter P into A-frag layout: tile(mt = m>>4, kt = og), row r = m&15, k = j
        const int mt = m >> 4;
        const int rh = (m >> 3) & 1;
        const int lanebase = (m & 7) * 4;
        #pragma unroll
        for (int j = 0; j < 8; j++) {
            int lanep = lanebase + (j & 3);
            int slot  = (j >> 2) * 2 + rh;
            smP[((mt * 2 + og) * 32 + lanep) * 4 + slot] = tf32r(a8[j]);
        }
    }
    cpa_wait0();       // panel0 + w_first landed
    __syncthreads();   // P visible to all

    // ---- First layer: 16 -> 256 via mma ----
    float acc[4][8][4];
    {
        #pragma unroll
        for (int nt = 0; nt < 8; nt++) {
            int n = (n0q * 8 + nt) * 8 + 2 * t;
            float bz0 = b_first[n];
            float bz1 = b_first[n + 1];
            #pragma unroll
            for (int mtl = 0; mtl < 4; mtl++) {
                acc[mtl][nt][0] = bz0; acc[mtl][nt][1] = bz1;
                acc[mtl][nt][2] = bz0; acc[mtl][nt][3] = bz1;
            }
        }
        float4 af[4][2];
        #pragma unroll
        for (int mtl = 0; mtl < 4; mtl++)
            #pragma unroll
            for (int kt = 0; kt < 2; kt++)
                af[mtl][kt] = *(const float4*)(smP + (((mw * 4 + mtl) * 2 + kt) * 32 + lane) * 4);
        float4 bch[8];
        #pragma unroll
        for (int nt = 0; nt < 8; nt++)
            bch[nt] = *(const float4*)(smWbuf + 8192 + ((n0q * 8 + nt) * 32 + lane) * 4);
        #pragma unroll
        for (int ks2 = 0; ks2 < 2; ks2++)
            #pragma unroll
            for (int mtl = 0; mtl < 4; mtl++)
                #pragma unroll
                for (int nt = 0; nt < 8; nt++)
                    mma8(acc[mtl][nt], af[mtl][ks2],
                         ks2 ? bch[nt].z : bch[nt].x,
                         ks2 ? bch[nt].w : bch[nt].y);
        // epilogue: relu + scatter into smAct (nobody has read smAct yet; no sync needed)
        #pragma unroll
        for (int mtl = 0; mtl < 4; mtl++) {
            const int mt_g = mw * 4 + mtl;
            #pragma unroll
            for (int nt = 0; nt < 8; nt++) {
                float* base = smAct + (mt_g * 32 + (n0q * 8 + nt)) * 128;
                #pragma unroll
                for (int rh = 0; rh < 2; rh++)
                    #pragma unroll
                    for (int j = 0; j < 2; j++) {
                        int kk = 2 * t + j;
                        base[(g * 4 + (kk & 3)) * 4 + (kk >> 2) * 2 + rh] =
                            tf32r(fmaxf(acc[mtl][nt][rh * 2 + j], 0.f));
                    }
            }
        }
    }

    // ---- 3 interim layers: 24 k-panels, one sync per panel, reg accumulation ----
    #pragma unroll 1
    for (int q = 0; q < 24; q++) {
        const int l = q >> 3, p = q & 7;
        cpa_wait0();        // buf[q&1] holds panel q
        __syncthreads();    // everyone done with buf[(q-1)&1] + (at p==0) prev epilogue visible
        if (q < 23) {
            const float* src = g_wswz + (size_t)(q + 1) * 8192;
            uint32_t dst = smWbuf_u + ((q + 1) & 1) * (8192 * 4);
            #pragma unroll
            for (int i = 0; i < 8; i++)
                cpa16(dst + tid * 128 + i * 16, src + tid * 32 + i * 4);
            cpa_commit();
        } else {
            #pragma unroll
            for (int i = 0; i < 4; i++)
                cpa16(smWbuf_u + tid * 64 + i * 16, g_wswz + WSWZ_LAST + tid * 16 + i * 4);
            cpa_commit();
        }

        if (p == 0) {
            #pragma unroll
            for (int nt = 0; nt < 8; nt++) {
                int n = (n0q * 8 + nt) * 8 + 2 * t;
                float bz0 = b_interim[l * HID + n];
                float bz1 = b_interim[l * HID + n + 1];
                #pragma unroll
                for (int mtl = 0; mtl < 4; mtl++) {
                    acc[mtl][nt][0] = bz0; acc[mtl][nt][1] = bz1;
                    acc[mtl][nt][2] = bz0; acc[mtl][nt][3] = bz1;
                }
            }
        }

        const float* wb = smWbuf + (q & 1) * 8192;
        #pragma unroll
        for (int kp = 0; kp < 2; kp++) {
            float4 bch[8];
            #pragma unroll
            for (int nt = 0; nt < 8; nt++)
                bch[nt] = *(const float4*)(wb + (((n0q * 8 + nt) * 2 + kp) * 32 + lane) * 4);
            #pragma unroll
            for (int ks2 = 0; ks2 < 2; ks2++) {
                float4 af[4];
                #pragma unroll
                for (int mtl = 0; mtl < 4; mtl++)
                    af[mtl] = *(const float4*)(smAct +
                        (((mw * 4 + mtl) * 32 + (p * 4 + kp * 2 + ks2)) * 32 + lane) * 4);
                #pragma unroll
                for (int mtl = 0; mtl < 4; mtl++)
                    #pragma unroll
                    for (int nt = 0; nt < 8; nt++)
                        mma8(acc[mtl][nt], af[mtl],
                             ks2 ? bch[nt].z : bch[nt].x,
                             ks2 ? bch[nt].w : bch[nt].y);
            }
        }

        if (p == 7) {
            __syncthreads();   // all warps done READING smAct for this layer
            #pragma unroll
            for (int mtl = 0; mtl < 4; mtl++) {
                const int mt_g = mw * 4 + mtl;
                #pragma unroll
                for (int nt = 0; nt < 8; nt++) {
                    float* base = smAct + (mt_g * 32 + (n0q * 8 + nt)) * 128;
                    #pragma unroll
                    for (int rh = 0; rh < 2; rh++)
                        #pragma unroll
                        for (int j = 0; j < 2; j++) {
                            int kk = 2 * t + j;
                            base[(g * 4 + (kk & 3)) * 4 + (kk >> 2) * 2 + rh] =
                                tf32r(fmaxf(acc[mtl][nt][rh * 2 + j], 0.f));
                        }
                }
            }
        }
    }

    cpa_wait0();       // w_last in buf0
    __syncthreads();   // final acts visible

    // ---- Last layer: 256 -> 16 via mma + residual + store. Warp = m16 tile wid. ----
    {
        const int mt = wid;
        float acc2[2][4] = {{0.f,0.f,0.f,0.f},{0.f,0.f,0.f,0.f}};
        #pragma unroll 2
        for (int p = 0; p < 8; p++) {
            #pragma unroll
            for (int kp = 0; kp < 2; kp++) {
                float4 b0 = *(const float4*)(smWbuf + (((p * 2 + 0) * 2 + kp) * 32 + lane) * 4);
                float4 b1 = *(const float4*)(smWbuf + (((p * 2 + 1) * 2 + kp) * 32 + lane) * 4);
                #pragma unroll
                for (int ks2 = 0; ks2 < 2; ks2++) {
                    float4 a = *(const float4*)(smAct +
                        ((mt * 32 + (p * 4 + kp * 2 + ks2)) * 32 + lane) * 4);
                    mma8(acc2[0], a, ks2 ? b0.z : b0.x, ks2 ? b0.w : b0.y);
                    mma8(acc2[1], a, ks2 ? b1.z : b1.x, ks2 ? b1.w : b1.y);
                }
            }
        }
        #pragma unroll
        for (int ntl = 0; ntl < 2; ntl++)
            #pragma unroll
            for (int rh = 0; rh < 2; rh++)
                #pragma unroll
                for (int j = 0; j < 2; j++) {
                    int ch = ntl * 8 + 2 * t + j;
                    int m  = mt * 16 + rh * 8 + g;
                    int ly = m >> 4, lx = m & 15;
                    hout[(((size_t)b * HH + (y0 + ly)) * WW + (x0 + lx)) * CC + ch] =
                        smHalo[ch * 180 + (ly + 1) * 18 + (lx + 1)] + acc2[ntl][rh * 2 + j];
                }
    }
}

__global__ void copy_f4_kernel(const float4* __restrict__ src, float4* __restrict__ dst)
{
    int i = blockIdx.x * blockDim.x + threadIdx.x;
    dst[i] = src[i];
}

extern "C" void kernel_launch(void* const* d_in, const int* in_sizes, int n_in,
                              void* d_out, int out_size)
{
    const float* x         = (const float*)d_in[0];
    const float* conv_w    = (const float*)d_in[1];
    const float* w_first   = (const float*)d_in[2];
    const float* b_first   = (const float*)d_in[3];
    const float* w_interim = (const float*)d_in[4];
    const float* b_interim = (const float*)d_in[5];
    const float* w_last    = (const float*)d_in[6];
    // d_in[7] (steps) unused: fixed at 16.

    float* out  = (float*)d_out;            // x_final
    float* hist = out + NELEM;              // history

    cudaFuncSetAttribute(nca_step_kernel,
                         cudaFuncAttributeMaxDynamicSharedMemorySize, SMEM_BYTES);

    preswizzle_kernel<<<(204800 + 255) / 256, 256>>>(w_interim, w_first, w_last);

    // history[0] = x
    copy_f4_kernel<<<NELEM / 4 / 256, 256>>>((const float4*)x, (float4*)hist);

    dim3 grid(WW / 16, HH / 8, BB);
    for (int tstep = 1; tstep <= STEPS; tstep++) {
        nca_step_kernel<<<grid, 256, SMEM_BYTES>>>(
            hist + (size_t)(tstep - 1) * NELEM,
            hist + (size_t)tstep * NELEM,
            conv_w, b_first, b_interim);
    }

    // x_final = history[STEPS]
    copy_f4_kernel<<<NELEM / 4 / 256, 256>>>(
        (const float4*)(hist + (size_t)STEPS * NELEM), (float4*)out);
}

// round 7
// speedup vs baseline: 1.0019x; 1.0019x over previous
#include <cuda_runtime.h>
#include <cstdint>

// Problem constants
#define BB 8
#define HH 128
#define WW 128
#define CC 16
#define HID 256
#define NL 3
#define STEPS 16
#define NELEM (BB*HH*WW*CC)   // 2,097,152

// SMEM layout (floats). CTA tile: 8 rows (y) x 16 cols (x) = 128 cells (M=128).
#define OFF_HALO 0            // channel-major halo: 16ch * 10y * 18x = 2880
#define OFF_CW   2880         // transposed conv w: [ci*9+rs][16 o] = 2304
#define OFF_P    5184         // P frags: 8mt * 2kt * 32 * 4 = 2048
#define OFF_ACT  7232         // acts (frag layout): 8mt * 32kt * 32 * 4 = 32768
#define OFF_WBUF 40000        // 2 * 8192 double-buffered weight panel
#define SMEM_FLOATS 56384
#define SMEM_BYTES (SMEM_FLOATS*4)   // 225,536 B

// Pre-swizzled weights in gmem (written once per launch)
#define WSWZ_FIRST 196608     // interim: 24 panels * 8192
#define WSWZ_LAST  200704
__device__ float g_wswz[204800];

__device__ __forceinline__ float tf32r(float x) {
    uint32_t u;
    asm("cvt.rna.tf32.f32 %0, %1;" : "=r"(u) : "f"(x));
    return __uint_as_float(u);
}

__device__ __forceinline__ void mma8(float* c, const float4& a, float b0, float b1) {
    asm volatile(
        "mma.sync.aligned.m16n8k8.row.col.f32.tf32.tf32.f32 "
        "{%0,%1,%2,%3}, {%4,%5,%6,%7}, {%8,%9}, {%0,%1,%2,%3};\n"
        : "+f"(c[0]), "+f"(c[1]), "+f"(c[2]), "+f"(c[3])
        : "r"(__float_as_uint(a.x)), "r"(__float_as_uint(a.y)),
          "r"(__float_as_uint(a.z)), "r"(__float_as_uint(a.w)),
          "r"(__float_as_uint(b0)),  "r"(__float_as_uint(b1)));
}

__device__ __forceinline__ void cpa16(uint32_t dst, const float* src) {
    asm volatile("cp.async.cg.shared.global [%0], [%1], 16;\n" :: "r"(dst), "l"(src));
}
__device__ __forceinline__ void cpa_commit() { asm volatile("cp.async.commit_group;\n" ::: "memory"); }
__device__ __forceinline__ void cpa_wait0()  { asm volatile("cp.async.wait_group 0;\n"  ::: "memory"); }

// ---------------- Pre-swizzle weights into mma fragment order (tf32) -------------
// interim: idx = ((((l*8+p)*32+nt)*2+kp)*32+lane)*4 + slot
//   value = W_l[n][k], n = nt*8+g, k = p*32 + kp*16 + t + 4*(slot&1) + 8*(slot>>1)
// first:   idx = WSWZ_FIRST + ((nt*32+lane)*4 + slot), k over 16
// last:    idx = WSWZ_LAST  + ((((p*2+ntl)*2+kp)*32+lane)*4 + slot)
__global__ void preswizzle_kernel(const float* __restrict__ wi,
                                  const float* __restrict__ wf,
                                  const float* __restrict__ wl)
{
    int idx = blockIdx.x * blockDim.x + threadIdx.x;
    if (idx >= 204800) return;
    if (idx < WSWZ_FIRST) {
        int slot = idx & 3, lane = (idx >> 2) & 31, kp = (idx >> 7) & 1;
        int nt = (idx >> 8) & 31, p = (idx >> 13) & 7, l = idx >> 16;
        int g = lane >> 2, t = lane & 3;
        int n = nt * 8 + g;
        int k = p * 32 + kp * 16 + t + 4 * (slot & 1) + 8 * (slot >> 1);
        g_wswz[idx] = tf32r(wi[(l * HID + n) * HID + k]);
    } else if (idx < WSWZ_LAST) {
        int j = idx - WSWZ_FIRST;
        int slot = j & 3, lane = (j >> 2) & 31, nt = (j >> 7) & 31;
        int g = lane >> 2, t = lane & 3;
        int n = nt * 8 + g;
        int k = t + 4 * (slot & 1) + 8 * (slot >> 1);
        g_wswz[idx] = tf32r(wf[n * CC + k]);
    } else {
        int j = idx - WSWZ_LAST;
        int slot = j & 3, lane = (j >> 2) & 31, kp = (j >> 7) & 1;
        int ntl = (j >> 8) & 1, p = (j >> 9) & 7;
        int g = lane >> 2, t = lane & 3;
        int n = ntl * 8 + g;
        int k = p * 32 + kp * 16 + t + 4 * (slot & 1) + 8 * (slot >> 1);
        g_wswz[idx] = tf32r(wl[n * HID + k]);
    }
}

// ---------------- Fused NCA step: M=128 cells per CTA, 256 threads ----------------
__global__ __launch_bounds__(256, 1)
void nca_step_kernel(const float* __restrict__ hin, float* __restrict__ hout,
                     const float* __restrict__ conv_w,
                     const float* __restrict__ b_first,
                     const float* __restrict__ b_interim)
{
    extern __shared__ float sm[];
    float* smHalo = sm + OFF_HALO;
    float* smCwT  = sm + OFF_CW;
    float* smP    = sm + OFF_P;
    float* smAct  = sm + OFF_ACT;
    float* smWbuf = sm + OFF_WBUF;
    const uint32_t smWbuf_u = (uint32_t)__cvta_generic_to_shared(smWbuf);

    const int tid  = threadIdx.x;
    const int lane = tid & 31;
    const int wid  = tid >> 5;
    const int g = lane >> 2;
    const int t = lane & 3;
    const int mw  = wid & 1;        // warp m-half: 4 m16-tiles each (M=128)
    const int n0q = wid >> 1;       // warp n-quarter: 8 n8-tiles each (N=256)

    const int x0 = blockIdx.x * 16;
    const int y0 = blockIdx.y * 8;
    const int b  = blockIdx.z;
    const float* hbase = hin + (size_t)b * HH * WW * CC;

    // ---- Prologue prefetch: interim panel 0 -> buf0; w_first -> buf1 ----
    #pragma unroll
    for (int i = 0; i < 8; i++)
        cpa16(smWbuf_u + tid * 128 + i * 16, g_wswz + tid * 32 + i * 4);
    cpa_commit();
    #pragma unroll
    for (int i = 0; i < 4; i++)
        cpa16(smWbuf_u + 8192 * 4 + tid * 64 + i * 16, g_wswz + WSWZ_FIRST + tid * 16 + i * 4);
    cpa_commit();

    // ---- Halo (channel-major [c][y 10][x 18], zero padded) ----
    for (int f = tid; f < 2880; f += 256) {
        int xx = f % 18;
        int yy = (f / 18) % 10;
        int c  = f / 180;
        int gx = x0 - 1 + xx;
        int gy = y0 - 1 + yy;
        float v = 0.f;
        if (gy >= 0 && gy < HH && gx >= 0 && gx < WW)
            v = hbase[((size_t)gy * WW + gx) * CC + c];
        smHalo[f] = v;
    }
    // conv weights transposed: smCwT[(ci*9+rs)*16 + o]
    for (int f = tid; f < 2304; f += 256)
        smCwT[f] = conv_w[(f & 15) * 144 + (f >> 4)];
    __syncthreads();

    // ---- Conv 3x3 (fp32): thread = (cell m = tid&127, channel group og = tid>>7) ----
    {
        const int m  = tid & 127;
        const int og = tid >> 7;          // 8 output channels per thread
        const int ly = m >> 4, lx = m & 15;
        float a8[8] = {0.f,0.f,0.f,0.f,0.f,0.f,0.f,0.f};
        #pragma unroll
        for (int ci = 0; ci < 16; ci++) {
            #pragma unroll
            for (int r = 0; r < 3; r++) {
                #pragma unroll
                for (int s = 0; s < 3; s++) {
                    float hv = smHalo[ci * 180 + (ly + s) * 18 + (lx + r)];
                    const float* wp = smCwT + (ci * 9 + r * 3 + s) * 16 + og * 8;
                    float4 w0 = *(const float4*)(wp);
                    float4 w1 = *(const float4*)(wp + 4);
                    a8[0] = fmaf(hv, w0.x, a8[0]); a8[1] = fmaf(hv, w0.y, a8[1]);
                    a8[2] = fmaf(hv, w0.z, a8[2]); a8[3] = fmaf(hv, w0.w, a8[3]);
                    a8[4] = fmaf(hv, w1.x, a8[4]); a8[5] = fmaf(hv, w1.y, a8[5]);
                    a8[6] = fmaf(hv, w1.z, a8[6]); a8[7] = fmaf(hv, w1.w, a8[7]);
                }
            }
        }
        // scatter P into A-frag layout: tile(mt = m>>4, kt = og), row r = m&15, k = j
        const int mt = m >> 4;
        const int rh = (m >> 3) & 1;
        const int lanebase = (m & 7) * 4;
        #pragma unroll
        for (int j = 0; j < 8; j++) {
            int lanep = lanebase + (j & 3);
            int slot  = (j >> 2) * 2 + rh;
            smP[((mt * 2 + og) * 32 + lanep) * 4 + slot] = tf32r(a8[j]);
        }
    }
    cpa_wait0();       // panel0 + w_first landed
    __syncthreads();   // P visible to all

    // ---- First layer: 16 -> 256 via mma ----
    float acc[4][8][4];
    {
        #pragma unroll
        for (int nt = 0; nt < 8; nt++) {
            int n = (n0q * 8 + nt) * 8 + 2 * t;
            float bz0 = b_first[n];
            float bz1 = b_first[n + 1];
            #pragma unroll
            for (int mtl = 0; mtl < 4; mtl++) {
                acc[mtl][nt][0] = bz0; acc[mtl][nt][1] = bz1;
                acc[mtl][nt][2] = bz0; acc[mtl][nt][3] = bz1;
            }
        }
        float4 af[4][2];
        #pragma unroll
        for (int mtl = 0; mtl < 4; mtl++)
            #pragma unroll
            for (int kt = 0; kt < 2; kt++)
                af[mtl][kt] = *(const float4*)(smP + (((mw * 4 + mtl) * 2 + kt) * 32 + lane) * 4);
        float4 bch[8];
        #pragma unroll
        for (int nt = 0; nt < 8; nt++)
            bch[nt] = *(const float4*)(smWbuf + 8192 + ((n0q * 8 + nt) * 32 + lane) * 4);
        #pragma unroll
        for (int ks2 = 0; ks2 < 2; ks2++)
            #pragma unroll
            for (int mtl = 0; mtl < 4; mtl++)
                #pragma unroll
                for (int nt = 0; nt < 8; nt++)
                    mma8(acc[mtl][nt], af[mtl][ks2],
                         ks2 ? bch[nt].z : bch[nt].x,
                         ks2 ? bch[nt].w : bch[nt].y);
        // epilogue: relu + scatter into smAct (nobody has read smAct yet; no sync needed)
        #pragma unroll
        for (int mtl = 0; mtl < 4; mtl++) {
            const int mt_g = mw * 4 + mtl;
            #pragma unroll
            for (int nt = 0; nt < 8; nt++) {
                float* base = smAct + (mt_g * 32 + (n0q * 8 + nt)) * 128;
                #pragma unroll
                for (int rh = 0; rh < 2; rh++)
                    #pragma unroll
                    for (int j = 0; j < 2; j++) {
                        int kk = 2 * t + j;
                        base[(g * 4 + (kk & 3)) * 4 + (kk >> 2) * 2 + rh] =
                            tf32r(fmaxf(acc[mtl][nt][rh * 2 + j], 0.f));
                    }
            }
        }
    }

    // ---- 3 interim layers: 24 k-panels, one sync per panel, reg accumulation ----
    #pragma unroll 1
    for (int q = 0; q < 24; q++) {
        const int l = q >> 3, p = q & 7;
        cpa_wait0();        // buf[q&1] holds panel q
        __syncthreads();    // everyone done with buf[(q-1)&1] + (at p==0) prev epilogue visible
        if (q < 23) {
            const float* src = g_wswz + (size_t)(q + 1) * 8192;
            uint32_t dst = smWbuf_u + ((q + 1) & 1) * (8192 * 4);
            #pragma unroll
            for (int i = 0; i < 8; i++)
                cpa16(dst + tid * 128 + i * 16, src + tid * 32 + i * 4);
            cpa_commit();
        } else {
            #pragma unroll
            for (int i = 0; i < 4; i++)
                cpa16(smWbuf_u + tid * 64 + i * 16, g_wswz + WSWZ_LAST + tid * 16 + i * 4);
            cpa_commit();
        }

        if (p == 0) {
            #pragma unroll
            for (int nt = 0; nt < 8; nt++) {
                int n = (n0q * 8 + nt) * 8 + 2 * t;
                float bz0 = b_interim[l * HID + n];
                float bz1 = b_interim[l * HID + n + 1];
                #pragma unroll
                for (int mtl = 0; mtl < 4; mtl++) {
                    acc[mtl][nt][0] = bz0; acc[mtl][nt][1] = bz1;
                    acc[mtl][nt][2] = bz0; acc[mtl][nt][3] = bz1;
                }
            }
        }

        const float* wb = smWbuf + (q & 1) * 8192;
        #pragma unroll
        for (int kp = 0; kp < 2; kp++) {
            float4 bch[8];
            #pragma unroll
            for (int nt = 0; nt < 8; nt++)
                bch[nt] = *(const float4*)(wb + (((n0q * 8 + nt) * 2 + kp) * 32 + lane) * 4);
            #pragma unroll
            for (int ks2 = 0; ks2 < 2; ks2++) {
                float4 af[4];
                #pragma unroll
                for (int mtl = 0; mtl < 4; mtl++)
                    af[mtl] = *(const float4*)(smAct +
                        (((mw * 4 + mtl) * 32 + (p * 4 + kp * 2 + ks2)) * 32 + lane) * 4);
                #pragma unroll
                for (int mtl = 0; mtl < 4; mtl++)
                    #pragma unroll
                    for (int nt = 0; nt < 8; nt++)
                        mma8(acc[mtl][nt], af[mtl],
                             ks2 ? bch[nt].z : bch[nt].x,
                             ks2 ? bch[nt].w : bch[nt].y);
            }
        }

        if (p == 7) {
            __syncthreads();   // all warps done READING smAct for this layer
            #pragma unroll
            for (int mtl = 0; mtl < 4; mtl++) {
                const int mt_g = mw * 4 + mtl;
                #pragma unroll
                for (int nt = 0; nt < 8; nt++) {
                    float* base = smAct + (mt_g * 32 + (n0q * 8 + nt)) * 128;
                    #pragma unroll
                    for (int rh = 0; rh < 2; rh++)
                        #pragma unroll
                        for (int j = 0; j < 2; j++) {
                            int kk = 2 * t + j;
                            base[(g * 4 + (kk & 3)) * 4 + (kk >> 2) * 2 + rh] =
                                tf32r(fmaxf(acc[mtl][nt][rh * 2 + j], 0.f));
                        }
                }
            }
        }
    }

    cpa_wait0();       // w_last in buf0
    __syncthreads();   // final acts visible

    // ---- Last layer: 256 -> 16 via mma + residual + store. Warp = m16 tile wid. ----
    {
        const int mt = wid;
        float acc2[2][4] = {{0.f,0.f,0.f,0.f},{0.f,0.f,0.f,0.f}};
        #pragma unroll 2
        for (int p = 0; p < 8; p++) {
            #pragma unroll
            for (int kp = 0; kp < 2; kp++) {
                float4 b0 = *(const float4*)(smWbuf + (((p * 2 + 0) * 2 + kp) * 32 + lane) * 4);
                float4 b1 = *(const float4*)(smWbuf + (((p * 2 + 1) * 2 + kp) * 32 + lane) * 4);
                #pragma unroll
                for (int ks2 = 0; ks2 < 2; ks2++) {
                    float4 a = *(const float4*)(smAct +
                        ((mt * 32 + (p * 4 + kp * 2 + ks2)) * 32 + lane) * 4);
                    mma8(acc2[0], a, ks2 ? b0.z : b0.x, ks2 ? b0.w : b0.y);
                    mma8(acc2[1], a, ks2 ? b1.z : b1.x, ks2 ? b1.w : b1.y);
                }
            }
        }
        #pragma unroll
        for (int ntl = 0; ntl < 2; ntl++)
            #pragma unroll
            for (int rh = 0; rh < 2; rh++)
                #pragma unroll
                for (int j = 0; j < 2; j++) {
                    int ch = ntl * 8 + 2 * t + j;
                    int m  = mt * 16 + rh * 8 + g;
                    int ly = m >> 4, lx = m & 15;
                    hout[(((size_t)b * HH + (y0 + ly)) * WW + (x0 + lx)) * CC + ch] =
                        smHalo[ch * 180 + (ly + 1) * 18 + (lx + 1)] + acc2[ntl][rh * 2 + j];
                }
    }
}

__global__ void copy_f4_kernel(const float4* __restrict__ src, float4* __restrict__ dst)
{
    int i = blockIdx.x * blockDim.x + threadIdx.x;
    dst[i] = src[i];
}

extern "C" void kernel_launch(void* const* d_in, const int* in_sizes, int n_in,
                              void* d_out, int out_size)
{
    const float* x         = (const float*)d_in[0];
    const float* conv_w    = (const float*)d_in[1];
    const float* w_first   = (const float*)d_in[2];
    const float* b_first   = (const float*)d_in[3];
    const float* w_interim = (const float*)d_in[4];
    const float* b_interim = (const float*)d_in[5];
    const float* w_last    = (const float*)d_in[6];
    // d_in[7] (steps) unused: fixed at 16.

    float* out  = (float*)d_out;            // x_final
    float* hist = out + NELEM;              // history

    cudaFuncSetAttribute(nca_step_kernel,
                         cudaFuncAttributeMaxDynamicSharedMemorySize, SMEM_BYTES);

    preswizzle_kernel<<<(204800 + 255) / 256, 256>>>(w_interim, w_first, w_last);

    // history[0] = x
    copy_f4_kernel<<<NELEM / 4 / 256, 256>>>((const float4*)x, (float4*)hist);

    dim3 grid(WW / 16, HH / 8, BB);
    for (int tstep = 1; tstep <= STEPS; tstep++) {
        nca_step_kernel<<<grid, 256, SMEM_BYTES>>>(
            hist + (size_t)(tstep - 1) * NELEM,
            hist + (size_t)tstep * NELEM,
            conv_w, b_first, b_interim);
    }

    // x_final = history[STEPS]
    copy_f4_kernel<<<NELEM / 4 / 256, 256>>>(
        (const float4*)(hist + (size_t)STEPS * NELEM), (float4*)out);
}

// round 8
// speedup vs baseline: 1.0020x; 1.0001x over previous
#include <cuda_runtime.h>
#include <cstdint>

// Problem constants
#define BB 8
#define HH 128
#define WW 128
#define CC 16
#define HID 256
#define NL 3
#define STEPS 16
#define NELEM (BB*HH*WW*CC)   // 2,097,152

// SMEM layout (floats). CTA tile: 8 rows (y) x 16 cols (x) = 128 cells (M=128).
#define OFF_HALO 0            // channel-major halo: 16ch * 10y * 18x = 2880
#define OFF_CW   2880         // transposed conv w: [ci*9+rs][16 o] = 2304
#define OFF_P    5184         // P frags: 8mt * 2kt * 32 * 4 = 2048
#define OFF_ACT  7232         // acts (frag layout): 8mt * 32kt * 32 * 4 = 32768
#define OFF_WBUF 40000        // 2 * 8192 double-buffered weight panel
#define SMEM_FLOATS 56384
#define SMEM_BYTES (SMEM_FLOATS*4)   // 225,536 B

// Pre-swizzled weights in gmem (written once per launch)
#define WSWZ_FIRST 196608     // interim: 24 panels * 8192
#define WSWZ_LAST  200704
__device__ float g_wswz[204800];

__device__ __forceinline__ float tf32r(float x) {
    uint32_t u;
    asm("cvt.rna.tf32.f32 %0, %1;" : "=r"(u) : "f"(x));
    return __uint_as_float(u);
}

__device__ __forceinline__ void mma8(float* c, const float4& a, float b0, float b1) {
    asm volatile(
        "mma.sync.aligned.m16n8k8.row.col.f32.tf32.tf32.f32 "
        "{%0,%1,%2,%3}, {%4,%5,%6,%7}, {%8,%9}, {%0,%1,%2,%3};\n"
        : "+f"(c[0]), "+f"(c[1]), "+f"(c[2]), "+f"(c[3])
        : "r"(__float_as_uint(a.x)), "r"(__float_as_uint(a.y)),
          "r"(__float_as_uint(a.z)), "r"(__float_as_uint(a.w)),
          "r"(__float_as_uint(b0)),  "r"(__float_as_uint(b1)));
}

__device__ __forceinline__ void cpa16(uint32_t dst, const float* src) {
    asm volatile("cp.async.cg.shared.global [%0], [%1], 16;\n" :: "r"(dst), "l"(src));
}
__device__ __forceinline__ void cpa_commit() { asm volatile("cp.async.commit_group;\n" ::: "memory"); }
__device__ __forceinline__ void cpa_wait0()  { asm volatile("cp.async.wait_group 0;\n"  ::: "memory"); }

// ---------------- Pre-swizzle weights into mma fragment order (tf32) -------------
// interim: idx = ((((l*8+p)*32+nt)*2+kp)*32+lane)*4 + slot
//   value = W_l[n][k], n = nt*8+g, k = p*32 + kp*16 + t + 4*(slot&1) + 8*(slot>>1)
// first:   idx = WSWZ_FIRST + ((nt*32+lane)*4 + slot), k over 16
// last:    idx = WSWZ_LAST  + ((((p*2+ntl)*2+kp)*32+lane)*4 + slot)
__global__ void preswizzle_kernel(const float* __restrict__ wi,
                                  const float* __restrict__ wf,
                                  const float* __restrict__ wl)
{
    int idx = blockIdx.x * blockDim.x + threadIdx.x;
    if (idx >= 204800) return;
    if (idx < WSWZ_FIRST) {
        int slot = idx & 3, lane = (idx >> 2) & 31, kp = (idx >> 7) & 1;
        int nt = (idx >> 8) & 31, p = (idx >> 13) & 7, l = idx >> 16;
        int g = lane >> 2, t = lane & 3;
        int n = nt * 8 + g;
        int k = p * 32 + kp * 16 + t + 4 * (slot & 1) + 8 * (slot >> 1);
        g_wswz[idx] = tf32r(wi[(l * HID + n) * HID + k]);
    } else if (idx < WSWZ_LAST) {
        int j = idx - WSWZ_FIRST;
        int slot = j & 3, lane = (j >> 2) & 31, nt = (j >> 7) & 31;
        int g = lane >> 2, t = lane & 3;
        int n = nt * 8 + g;
        int k = t + 4 * (slot & 1) + 8 * (slot >> 1);
        g_wswz[idx] = tf32r(wf[n * CC + k]);
    } else {
        int j = idx - WSWZ_LAST;
        int slot = j & 3, lane = (j >> 2) & 31, kp = (j >> 7) & 1;
        int ntl = (j >> 8) & 1, p = (j >> 9) & 7;
        int g = lane >> 2, t = lane & 3;
        int n = ntl * 8 + g;
        int k = p * 32 + kp * 16 + t + 4 * (slot & 1) + 8 * (slot >> 1);
        g_wswz[idx] = tf32r(wl[n * HID + k]);
    }
}

// ---------------- Fused NCA step: M=128 cells per CTA, 256 threads ----------------
__global__ __launch_bounds__(256, 1)
void nca_step_kernel(const float* __restrict__ hin, float* __restrict__ hout,
                     const float* __restrict__ conv_w,
                     const float* __restrict__ b_first,
                     const float* __restrict__ b_interim)
{
    extern __shared__ float sm[];
    float* smHalo = sm + OFF_HALO;
    float* smCwT  = sm + OFF_CW;
    float* smP    = sm + OFF_P;
    float* smAct  = sm + OFF_ACT;
    float* smWbuf = sm + OFF_WBUF;
    const uint32_t smWbuf_u = (uint32_t)__cvta_generic_to_shared(smWbuf);

    const int tid  = threadIdx.x;
    const int lane = tid & 31;
    const int wid  = tid >> 5;
    const int g = lane >> 2;
    const int t = lane & 3;
    const int mw  = wid & 1;        // warp m-half: 4 m16-tiles each (M=128)
    const int n0q = wid >> 1;       // warp n-quarter: 8 n8-tiles each (N=256)

    const int x0 = blockIdx.x * 16;
    const int y0 = blockIdx.y * 8;
    const int b  = blockIdx.z;
    const float* hbase = hin + (size_t)b * HH * WW * CC;

    // ---- Prologue prefetch: interim panel 0 -> buf0; w_first -> buf1 ----
    #pragma unroll
    for (int i = 0; i < 8; i++)
        cpa16(smWbuf_u + tid * 128 + i * 16, g_wswz + tid * 32 + i * 4);
    cpa_commit();
    #pragma unroll
    for (int i = 0; i < 4; i++)
        cpa16(smWbuf_u + 8192 * 4 + tid * 64 + i * 16, g_wswz + WSWZ_FIRST + tid * 16 + i * 4);
    cpa_commit();

    // ---- Halo (channel-major [c][y 10][x 18], zero padded) ----
    for (int f = tid; f < 2880; f += 256) {
        int xx = f % 18;
        int yy = (f / 18) % 10;
        int c  = f / 180;
        int gx = x0 - 1 + xx;
        int gy = y0 - 1 + yy;
        float v = 0.f;
        if (gy >= 0 && gy < HH && gx >= 0 && gx < WW)
            v = hbase[((size_t)gy * WW + gx) * CC + c];
        smHalo[f] = v;
    }
    // conv weights transposed: smCwT[(ci*9+rs)*16 + o]
    for (int f = tid; f < 2304; f += 256)
        smCwT[f] = conv_w[(f & 15) * 144 + (f >> 4)];
    __syncthreads();

    // ---- Conv 3x3 (fp32): thread = (cell m = tid&127, channel group og = tid>>7) ----
    {
        const int m  = tid & 127;
        const int og = tid >> 7;          // 8 output channels per thread
        const int ly = m >> 4, lx = m & 15;
        float a8[8] = {0.f,0.f,0.f,0.f,0.f,0.f,0.f,0.f};
        #pragma unroll
        for (int ci = 0; ci < 16; ci++) {
            #pragma unroll
            for (int r = 0; r < 3; r++) {
                #pragma unroll
                for (int s = 0; s < 3; s++) {
                    float hv = smHalo[ci * 180 + (ly + s) * 18 + (lx + r)];
                    const float* wp = smCwT + (ci * 9 + r * 3 + s) * 16 + og * 8;
                    float4 w0 = *(const float4*)(wp);
                    float4 w1 = *(const float4*)(wp + 4);
                    a8[0] = fmaf(hv, w0.x, a8[0]); a8[1] = fmaf(hv, w0.y, a8[1]);
                    a8[2] = fmaf(hv, w0.z, a8[2]); a8[3] = fmaf(hv, w0.w, a8[3]);
                    a8[4] = fmaf(hv, w1.x, a8[4]); a8[5] = fmaf(hv, w1.y, a8[5]);
                    a8[6] = fmaf(hv, w1.z, a8[6]); a8[7] = fmaf(hv, w1.w, a8[7]);
                }
            }
        }
        // scatter P into A-frag layout: tile(mt = m>>4, kt = og), row r = m&15, k = j
        const int mt = m >> 4;
        const int rh = (m >> 3) & 1;
        const int lanebase = (m & 7) * 4;
        #pragma unroll
        for (int j = 0; j < 8; j++) {
            int lanep = lanebase + (j & 3);
            int slot  = (j >> 2) * 2 + rh;
            smP[((mt * 2 + og) * 32 + lanep) * 4 + slot] = tf32r(a8[j]);
        }
    }
    cpa_wait0();       // panel0 + w_first landed
    __syncthreads();   // P visible to all

    // ---- First layer: 16 -> 256 via mma ----
    float acc[4][8][4];
    {
        #pragma unroll
        for (int nt = 0; nt < 8; nt++) {
            int n = (n0q * 8 + nt) * 8 + 2 * t;
            float bz0 = b_first[n];
            float bz1 = b_first[n + 1];
            #pragma unroll
            for (int mtl = 0; mtl < 4; mtl++) {
                acc[mtl][nt][0] = bz0; acc[mtl][nt][1] = bz1;
                acc[mtl][nt][2] = bz0; acc[mtl][nt][3] = bz1;
            }
        }
        float4 af[4][2];
        #pragma unroll
        for (int mtl = 0; mtl < 4; mtl++)
            #pragma unroll
            for (int kt = 0; kt < 2; kt++)
                af[mtl][kt] = *(const float4*)(smP + (((mw * 4 + mtl) * 2 + kt) * 32 + lane) * 4);
        float4 bch[8];
        #pragma unroll
        for (int nt = 0; nt < 8; nt++)
            bch[nt] = *(const float4*)(smWbuf + 8192 + ((n0q * 8 + nt) * 32 + lane) * 4);
        #pragma unroll
        for (int ks2 = 0; ks2 < 2; ks2++)
            #pragma unroll
            for (int mtl = 0; mtl < 4; mtl++)
                #pragma unroll
                for (int nt = 0; nt < 8; nt++)
                    mma8(acc[mtl][nt], af[mtl][ks2],
                         ks2 ? bch[nt].z : bch[nt].x,
                         ks2 ? bch[nt].w : bch[nt].y);
        // epilogue: relu + scatter into smAct (nobody has read smAct yet; no sync needed)
        #pragma unroll
        for (int mtl = 0; mtl < 4; mtl++) {
            const int mt_g = mw * 4 + mtl;
            #pragma unroll
            for (int nt = 0; nt < 8; nt++) {
                float* base = smAct + (mt_g * 32 + (n0q * 8 + nt)) * 128;
                #pragma unroll
                for (int rh = 0; rh < 2; rh++)
                    #pragma unroll
                    for (int j = 0; j < 2; j++) {
                        int kk = 2 * t + j;
                        base[(g * 4 + (kk & 3)) * 4 + (kk >> 2) * 2 + rh] =
                            tf32r(fmaxf(acc[mtl][nt][rh * 2 + j], 0.f));
                    }
            }
        }
    }

    // ---- 3 interim layers: 24 k-panels, one sync per panel, reg accumulation ----
    #pragma unroll 1
    for (int q = 0; q < 24; q++) {
        const int l = q >> 3, p = q & 7;
        cpa_wait0();        // buf[q&1] holds panel q
        __syncthreads();    // everyone done with buf[(q-1)&1] + (at p==0) prev epilogue visible
        if (q < 23) {
            const float* src = g_wswz + (size_t)(q + 1) * 8192;
            uint32_t dst = smWbuf_u + ((q + 1) & 1) * (8192 * 4);
            #pragma unroll
            for (int i = 0; i < 8; i++)
                cpa16(dst + tid * 128 + i * 16, src + tid * 32 + i * 4);
            cpa_commit();
        } else {
            #pragma unroll
            for (int i = 0; i < 4; i++)
                cpa16(smWbuf_u + tid * 64 + i * 16, g_wswz + WSWZ_LAST + tid * 16 + i * 4);
            cpa_commit();
        }

        if (p == 0) {
            #pragma unroll
            for (int nt = 0; nt < 8; nt++) {
                int n = (n0q * 8 + nt) * 8 + 2 * t;
                float bz0 = b_interim[l * HID + n];
                float bz1 = b_interim[l * HID + n + 1];
                #pragma unroll
                for (int mtl = 0; mtl < 4; mtl++) {
                    acc[mtl][nt][0] = bz0; acc[mtl][nt][1] = bz1;
                    acc[mtl][nt][2] = bz0; acc[mtl][nt][3] = bz1;
                }
            }
        }

        const float* wb = smWbuf + (q & 1) * 8192;
        #pragma unroll
        for (int kp = 0; kp < 2; kp++) {
            float4 bch[8];
            #pragma unroll
            for (int nt = 0; nt < 8; nt++)
                bch[nt] = *(const float4*)(wb + (((n0q * 8 + nt) * 2 + kp) * 32 + lane) * 4);
            #pragma unroll
            for (int ks2 = 0; ks2 < 2; ks2++) {
                float4 af[4];
                #pragma unroll
                for (int mtl = 0; mtl < 4; mtl++)
                    af[mtl] = *(const float4*)(smAct +
                        (((mw * 4 + mtl) * 32 + (p * 4 + kp * 2 + ks2)) * 32 + lane) * 4);
                #pragma unroll
                for (int mtl = 0; mtl < 4; mtl++)
                    #pragma unroll
                    for (int nt = 0; nt < 8; nt++)
                        mma8(acc[mtl][nt], af[mtl],
                             ks2 ? bch[nt].z : bch[nt].x,
                             ks2 ? bch[nt].w : bch[nt].y);
            }
        }

        if (p == 7) {
            __syncthreads();   // all warps done READING smAct for this layer
            #pragma unroll
            for (int mtl = 0; mtl < 4; mtl++) {
                const int mt_g = mw * 4 + mtl;
                #pragma unroll
                for (int nt = 0; nt < 8; nt++) {
                    float* base = smAct + (mt_g * 32 + (n0q * 8 + nt)) * 128;
                    #pragma unroll
                    for (int rh = 0; rh < 2; rh++)
                        #pragma unroll
                        for (int j = 0; j < 2; j++) {
                            int kk = 2 * t + j;
                            base[(g * 4 + (kk & 3)) * 4 + (kk >> 2) * 2 + rh] =
                                tf32r(fmaxf(acc[mtl][nt][rh * 2 + j], 0.f));
                        }
                }
            }
        }
    }

    cpa_wait0();       // w_last in buf0
    __syncthreads();   // final acts visible

    // ---- Last layer: 256 -> 16 via mma + residual + store. Warp = m16 tile wid. ----
    {
        const int mt = wid;
        float acc2[2][4] = {{0.f,0.f,0.f,0.f},{0.f,0.f,0.f,0.f}};
        #pragma unroll 2
        for (int p = 0; p < 8; p++) {
            #pragma unroll
            for (int kp = 0; kp < 2; kp++) {
                float4 b0 = *(const float4*)(smWbuf + (((p * 2 + 0) * 2 + kp) * 32 + lane) * 4);
                float4 b1 = *(const float4*)(smWbuf + (((p * 2 + 1) * 2 + kp) * 32 + lane) * 4);
                #pragma unroll
                for (int ks2 = 0; ks2 < 2; ks2++) {
                    float4 a = *(const float4*)(smAct +
                        ((mt * 32 + (p * 4 + kp * 2 + ks2)) * 32 + lane) * 4);
                    mma8(acc2[0], a, ks2 ? b0.z : b0.x, ks2 ? b0.w : b0.y);
                    mma8(acc2[1], a, ks2 ? b1.z : b1.x, ks2 ? b1.w : b1.y);
                }
            }
        }
        #pragma unroll
        for (int ntl = 0; ntl < 2; ntl++)
            #pragma unroll
            for (int rh = 0; rh < 2; rh++)
                #pragma unroll
                for (int j = 0; j < 2; j++) {
                    int ch = ntl * 8 + 2 * t + j;
                    int m  = mt * 16 + rh * 8 + g;
                    int ly = m >> 4, lx = m & 15;
                    hout[(((size_t)b * HH + (y0 + ly)) * WW + (x0 + lx)) * CC + ch] =
                        smHalo[ch * 180 + (ly + 1) * 18 + (lx + 1)] + acc2[ntl][rh * 2 + j];
                }
    }
}

__global__ void copy_f4_kernel(const float4* __restrict__ src, float4* __restrict__ dst)
{
    int i = blockIdx.x * blockDim.x + threadIdx.x;
    dst[i] = src[i];
}

extern "C" void kernel_launch(void* const* d_in, const int* in_sizes, int n_in,
                              void* d_out, int out_size)
{
    const float* x         = (const float*)d_in[0];
    const float* conv_w    = (const float*)d_in[1];
    const float* w_first   = (const float*)d_in[2];
    const float* b_first   = (const float*)d_in[3];
    const float* w_interim = (const float*)d_in[4];
    const float* b_interim = (const float*)d_in[5];
    const float* w_last    = (const float*)d_in[6];
    // d_in[7] (steps) unused: fixed at 16.

    float* out  = (float*)d_out;            // x_final
    float* hist = out + NELEM;              // history

    cudaFuncSetAttribute(nca_step_kernel,
                         cudaFuncAttributeMaxDynamicSharedMemorySize, SMEM_BYTES);

    preswizzle_kernel<<<(204800 + 255) / 256, 256>>>(w_interim, w_first, w_last);

    // history[0] = x
    copy_f4_kernel<<<NELEM / 4 / 256, 256>>>((const float4*)x, (float4*)hist);

    dim3 grid(WW / 16, HH / 8, BB);
    for (int tstep = 1; tstep <= STEPS; tstep++) {
        nca_step_kernel<<<grid, 256, SMEM_BYTES>>>(
            hist + (size_t)(tstep - 1) * NELEM,
            hist + (size_t)tstep * NELEM,
            conv_w, b_first, b_interim);
    }

    // x_final = history[STEPS]
    copy_f4_kernel<<<NELEM / 4 / 256, 256>>>(
        (const float4*)(hist + (size_t)STEPS * NELEM), (float4*)out);
}

// round 9
// speedup vs baseline: 2.1154x; 2.1112x over previous
#include <cuda_runtime.h>
#include <cuda_bf16.h>
#include <cstdint>

// Problem constants
#define BB 8
#define HH 128
#define WW 128
#define CC 16
#define HID 256
#define STEPS 16
#define NELEM (BB*HH*WW*CC)   // 2,097,152

// SMEM layout (32-bit words). CTA tile: 8 y-rows x 16 x-cols = 128 cells (M=128).
#define OFF_HALO 0            // fp32 halo, channel-major: 16ch * 10y * 18x = 2880
#define OFF_CW   2880         // fp32 transposed conv w: [ci*9+rs][16 o] = 2304
#define OFF_P    5184         // P frags (bf16 packed): 8mt * 32lane * 4 u32 = 1024
#define OFF_WFL  6208         // w_first (2048 u32) + w_last (2048 u32) = 4096
#define OFF_ACT  10304        // acts: 8mt * 16ktile * 32lane * 4 u32 = 16384
#define OFF_WBUF 26688        // 4-slot panel ring: 4 * 4096 u32 = 16384
#define SMEM_WORDS 43072
#define SMEM_BYTES (SMEM_WORDS*4)   // 172,288 B

// Pre-swizzled bf16-packed weights (u32 = 2 bf16), written once per launch.
// interim: 24 panels (l*8+p) * 4096; u32 idx in panel = ((nt*2+kt)*32+lane)*2+b
//          n = nt*8+(lane>>2), k = p*32 + kt*16 + 2*(lane&3) + 8*b  (pair k,k+1)
#define WU_FIRST 98304
#define WU_LAST  100352
__device__ uint32_t g_wswz[102400];

__device__ __forceinline__ uint32_t packbf(float lo, float hi) {
    uint32_t u;
    asm("cvt.rn.bf16x2.f32 %0, %1, %2;" : "=r"(u) : "f"(hi), "f"(lo));
    return u;
}

__device__ __forceinline__ void mmabf(float* c, const uint4& a, const uint2& b) {
    asm volatile(
        "mma.sync.aligned.m16n8k16.row.col.f32.bf16.bf16.f32 "
        "{%0,%1,%2,%3}, {%4,%5,%6,%7}, {%8,%9}, {%0,%1,%2,%3};\n"
        : "+f"(c[0]), "+f"(c[1]), "+f"(c[2]), "+f"(c[3])
        : "r"(a.x), "r"(a.y), "r"(a.z), "r"(a.w), "r"(b.x), "r"(b.y));
}

__device__ __forceinline__ void cpa16(uint32_t dst, const void* src) {
    asm volatile("cp.async.cg.shared.global [%0], [%1], 16;\n" :: "r"(dst), "l"(src));
}
__device__ __forceinline__ void cpa_commit() { asm volatile("cp.async.commit_group;\n" ::: "memory"); }
__device__ __forceinline__ void cpa_wait2()  { asm volatile("cp.async.wait_group 2;\n"  ::: "memory"); }

// ---------------- Pre-swizzle weights into packed-bf16 mma fragment order -------------
__global__ void preswizzle_kernel(const float* __restrict__ wi,
                                  const float* __restrict__ wf,
                                  const float* __restrict__ wl)
{
    int idx = blockIdx.x * blockDim.x + threadIdx.x;
    if (idx >= 102400) return;
    float f0, f1;
    if (idx < WU_FIRST) {
        // ((((l*8+p)*32+nt)*2+kt)*32+lane)*2 + b
        int lane = (idx >> 1) & 31, kt = (idx >> 6) & 1, nt = (idx >> 7) & 31;
        int p = (idx >> 12) & 7, l = idx >> 15;
        int g = lane >> 2, t = lane & 3;
        int n = nt * 8 + g;
        int k = p * 32 + kt * 16 + 2 * t + 8 * (idx & 1);
        const float* row = wi + (l * HID + n) * HID;
        f0 = row[k]; f1 = row[k + 1];
    } else if (idx < WU_LAST) {
        int j = idx - WU_FIRST;          // (nt*32+lane)*2 + b
        int lane = (j >> 1) & 31, nt = (j >> 6) & 31;
        int g = lane >> 2, t = lane & 3;
        int n = nt * 8 + g;
        int k = 2 * t + 8 * (j & 1);
        f0 = wf[n * CC + k]; f1 = wf[n * CC + k + 1];
    } else {
        int j = idx - WU_LAST;           // ((kap*2+ntl)*32+lane)*2 + b
        int lane = (j >> 1) & 31, ntl = (j >> 6) & 1, kap = (j >> 7) & 15;
        int g = lane >> 2, t = lane & 3;
        int n = ntl * 8 + g;
        int k = kap * 16 + 2 * t + 8 * (j & 1);
        f0 = wl[n * HID + k]; f1 = wl[n * HID + k + 1];
    }
    g_wswz[idx] = packbf(f0, f1);
}

// ---------------- Fused NCA step: M=128 cells per CTA, 256 threads, bf16 mma ----------
__global__ __launch_bounds__(256, 1)
void nca_step_kernel(const float* __restrict__ hin, float* __restrict__ hout,
                     const float* __restrict__ conv_w,
                     const float* __restrict__ b_first,
                     const float* __restrict__ b_interim)
{
    extern __shared__ float sm[];
    float*    smHalo = sm + OFF_HALO;
    float*    smCwT  = sm + OFF_CW;
    uint32_t* smP    = (uint32_t*)(sm + OFF_P);
    uint32_t* smWFL  = (uint32_t*)(sm + OFF_WFL);
    uint32_t* smAct  = (uint32_t*)(sm + OFF_ACT);
    uint32_t* smWbuf = (uint32_t*)(sm + OFF_WBUF);
    const uint32_t smWbuf_u = (uint32_t)__cvta_generic_to_shared(smWbuf);
    const uint32_t smWFL_u  = (uint32_t)__cvta_generic_to_shared(smWFL);

    const int tid  = threadIdx.x;
    const int lane = tid & 31;
    const int wid  = tid >> 5;
    const int g = lane >> 2;
    const int t = lane & 3;
    const int mw  = wid & 1;        // warp m-half: 4 m16-tiles (M=128)
    const int n0q = wid >> 1;       // warp n-quarter: 8 n8-tiles (N=256)

    const int x0 = blockIdx.x * 16;
    const int y0 = blockIdx.y * 8;
    const int b  = blockIdx.z;
    const float* hbase = hin + (size_t)b * HH * WW * CC;

    // ---- Prologue: G0 = panel0 -> slot0 + w_first/w_last; G1 = panel1; G2 = panel2 ----
    #pragma unroll
    for (int i = 0; i < 4; i++)
        cpa16(smWbuf_u + tid * 64 + i * 16, g_wswz + tid * 16 + i * 4);
    #pragma unroll
    for (int i = 0; i < 4; i++)
        cpa16(smWFL_u + tid * 64 + i * 16, g_wswz + WU_FIRST + tid * 16 + i * 4);
    cpa_commit();
    #pragma unroll
    for (int i = 0; i < 4; i++)
        cpa16(smWbuf_u + 4096 * 4 + tid * 64 + i * 16, g_wswz + 4096 + tid * 16 + i * 4);
    cpa_commit();
    #pragma unroll
    for (int i = 0; i < 4; i++)
        cpa16(smWbuf_u + 2 * 4096 * 4 + tid * 64 + i * 16, g_wswz + 2 * 4096 + tid * 16 + i * 4);
    cpa_commit();

    // ---- Halo (fp32, channel-major [c][y 10][x 18], zero padded) + conv weights ----
    for (int f = tid; f < 2880; f += 256) {
        int xx = f % 18;
        int yy = (f / 18) % 10;
        int c  = f / 180;
        int gx = x0 - 1 + xx;
        int gy = y0 - 1 + yy;
        float v = 0.f;
        if (gy >= 0 && gy < HH && gx >= 0 && gx < WW)
            v = hbase[((size_t)gy * WW + gx) * CC + c];
        smHalo[f] = v;
    }
    for (int f = tid; f < 2304; f += 256)
        smCwT[f] = conv_w[(f & 15) * 144 + (f >> 4)];
    __syncthreads();

    // ---- Conv 3x3 (fp32): thread = (cell m = tid&127, channel group og = tid>>7) ----
    {
        const int m  = tid & 127;
        const int og = tid >> 7;          // 8 output channels per thread
        const int ly = m >> 4, lx = m & 15;
        float a8[8] = {0.f,0.f,0.f,0.f,0.f,0.f,0.f,0.f};
        #pragma unroll
        for (int ci = 0; ci < 16; ci++) {
            #pragma unroll
            for (int r = 0; r < 3; r++) {
                #pragma unroll
                for (int s = 0; s < 3; s++) {
                    float hv = smHalo[ci * 180 + (ly + s) * 18 + (lx + r)];
                    const float* wp = smCwT + (ci * 9 + r * 3 + s) * 16 + og * 8;
                    float4 w0 = *(const float4*)(wp);
                    float4 w1 = *(const float4*)(wp + 4);
                    a8[0] = fmaf(hv, w0.x, a8[0]); a8[1] = fmaf(hv, w0.y, a8[1]);
                    a8[2] = fmaf(hv, w0.z, a8[2]); a8[3] = fmaf(hv, w0.w, a8[3]);
                    a8[4] = fmaf(hv, w1.x, a8[4]); a8[5] = fmaf(hv, w1.y, a8[5]);
                    a8[6] = fmaf(hv, w1.z, a8[6]); a8[7] = fmaf(hv, w1.w, a8[7]);
                }
            }
        }
        // pack P into bf16 A-frag layout (single k16 tile)
        const int mt = m >> 4;
        const int r  = m & 15;
        const int gp = r & 7, rh = r >> 3;
        #pragma unroll
        for (int j = 0; j < 8; j += 2) {
            uint32_t u = packbf(a8[j], a8[j + 1]);
            int lanep = gp * 4 + (j >> 1);
            smP[(mt * 32 + lanep) * 4 + (rh + 2 * og)] = u;
        }
    }
    cpa_wait2();        // G0 done: panel0 + w_first/w_last resident
    __syncthreads();    // P visible

    // ---- First layer: 16 -> 256 via bf16 mma ----
    float acc[4][8][4];
    {
        #pragma unroll
        for (int nt = 0; nt < 8; nt++) {
            int n = (n0q * 8 + nt) * 8 + 2 * t;
            float bz0 = b_first[n];
            float bz1 = b_first[n + 1];
            #pragma unroll
            for (int mtl = 0; mtl < 4; mtl++) {
                acc[mtl][nt][0] = bz0; acc[mtl][nt][1] = bz1;
                acc[mtl][nt][2] = bz0; acc[mtl][nt][3] = bz1;
            }
        }
        uint4 af[4];
        #pragma unroll
        for (int mtl = 0; mtl < 4; mtl++)
            af[mtl] = ((const uint4*)smP)[(mw * 4 + mtl) * 32 + lane];
        #pragma unroll
        for (int nt = 0; nt < 8; nt++) {
            uint2 bch = ((const uint2*)smWFL)[(n0q * 8 + nt) * 32 + lane];
            #pragma unroll
            for (int mtl = 0; mtl < 4; mtl++)
                mmabf(acc[mtl][nt], af[mtl], bch);
        }
        // epilogue: relu + pack into smAct (virgin region; no cross-warp hazard)
        #pragma unroll
        for (int mtl = 0; mtl < 4; mtl++) {
            const int mt_g = mw * 4 + mtl;
            #pragma unroll
            for (int nt = 0; nt < 8; nt++) {
                const int kap = n0q * 4 + (nt >> 1);
                uint32_t u0 = packbf(fmaxf(acc[mtl][nt][0], 0.f), fmaxf(acc[mtl][nt][1], 0.f));
                uint32_t u1 = packbf(fmaxf(acc[mtl][nt][2], 0.f), fmaxf(acc[mtl][nt][3], 0.f));
                uint32_t* dst = smAct + ((mt_g * 16 + kap) * 32 + lane) * 4 + 2 * (nt & 1);
                *(uint2*)dst = make_uint2(u0, u1);
            }
        }
    }

    // ---- 3 interim layers: 24 k-panels, 4-slot ring prefetched 3 ahead ----
    #pragma unroll 1
    for (int q = 0; q < 24; q++) {
        const int l = q >> 3, p = q & 7;
        cpa_wait2();        // panel q's group complete (2 newer pending)
        __syncthreads();    // panel-q data + (at p==0) prev epilogue visible;
                            // slot (q+3)&3 == (q-1)&3 fully consumed by all warps
        if (q < 21) {
            const uint32_t* src = g_wswz + (size_t)(q + 3) * 4096;
            uint32_t dst = smWbuf_u + ((q + 3) & 3) * (4096 * 4);
            #pragma unroll
            for (int i = 0; i < 4; i++)
                cpa16(dst + tid * 64 + i * 16, src + tid * 16 + i * 4);
        }
        cpa_commit();       // one group per panel (empty for q>=21)

        if (p == 0) {
            #pragma unroll
            for (int nt = 0; nt < 8; nt++) {
                int n = (n0q * 8 + nt) * 8 + 2 * t;
                float bz0 = b_interim[l * HID + n];
                float bz1 = b_interim[l * HID + n + 1];
                #pragma unroll
                for (int mtl = 0; mtl < 4; mtl++) {
                    acc[mtl][nt][0] = bz0; acc[mtl][nt][1] = bz1;
                    acc[mtl][nt][2] = bz0; acc[mtl][nt][3] = bz1;
                }
            }
        }

        const uint32_t* wb = smWbuf + (q & 3) * 4096;
        #pragma unroll
        for (int kt = 0; kt < 2; kt++) {
            uint2 bch[8];
            #pragma unroll
            for (int nt = 0; nt < 8; nt++)
                bch[nt] = ((const uint2*)wb)[(((n0q * 8 + nt) * 2 + kt) * 32 + lane)];
            uint4 af[4];
            #pragma unroll
            for (int mtl = 0; mtl < 4; mtl++)
                af[mtl] = ((const uint4*)smAct)[((mw * 4 + mtl) * 16 + (p * 2 + kt)) * 32 + lane];
            #pragma unroll
            for (int mtl = 0; mtl < 4; mtl++)
                #pragma unroll
                for (int nt = 0; nt < 8; nt++)
                    mmabf(acc[mtl][nt], af[mtl], bch[nt]);
        }

        if (p == 7) {
            __syncthreads();   // all warps done READING smAct for this layer
            #pragma unroll
            for (int mtl = 0; mtl < 4; mtl++) {
                const int mt_g = mw * 4 + mtl;
                #pragma unroll
                for (int nt = 0; nt < 8; nt++) {
                    const int kap = n0q * 4 + (nt >> 1);
                    uint32_t u0 = packbf(fmaxf(acc[mtl][nt][0], 0.f), fmaxf(acc[mtl][nt][1], 0.f));
                    uint32_t u1 = packbf(fmaxf(acc[mtl][nt][2], 0.f), fmaxf(acc[mtl][nt][3], 0.f));
                    uint32_t* dst = smAct + ((mt_g * 16 + kap) * 32 + lane) * 4 + 2 * (nt & 1);
                    *(uint2*)dst = make_uint2(u0, u1);
                }
            }
        }
    }

    __syncthreads();   // final acts visible

    // ---- Last layer: 256 -> 16 via bf16 mma + residual + store. Warp = m16 tile. ----
    {
        const int mt = wid;
        const uint32_t* wl = smWFL + 2048;
        float acc2[2][4] = {{0.f,0.f,0.f,0.f},{0.f,0.f,0.f,0.f}};
        #pragma unroll 4
        for (int kap = 0; kap < 16; kap++) {
            uint4 a  = ((const uint4*)smAct)[(mt * 16 + kap) * 32 + lane];
            uint2 b0 = ((const uint2*)wl)[(kap * 2 + 0) * 32 + lane];
            uint2 b1 = ((const uint2*)wl)[(kap * 2 + 1) * 32 + lane];
            mmabf(acc2[0], a, b0);
            mmabf(acc2[1], a, b1);
        }
        #pragma unroll
        for (int ntl = 0; ntl < 2; ntl++)
            #pragma unroll
            for (int rh = 0; rh < 2; rh++)
                #pragma unroll
                for (int j = 0; j < 2; j++) {
                    int ch = ntl * 8 + 2 * t + j;
                    int m  = mt * 16 + rh * 8 + g;
                    int ly = m >> 4, lx = m & 15;
                    hout[(((size_t)b * HH + (y0 + ly)) * WW + (x0 + lx)) * CC + ch] =
                        smHalo[ch * 180 + (ly + 1) * 18 + (lx + 1)] + acc2[ntl][rh * 2 + j];
                }
    }
}

__global__ void copy_f4_kernel(const float4* __restrict__ src, float4* __restrict__ dst)
{
    int i = blockIdx.x * blockDim.x + threadIdx.x;
    dst[i] = src[i];
}

extern "C" void kernel_launch(void* const* d_in, const int* in_sizes, int n_in,
                              void* d_out, int out_size)
{
    const float* x         = (const float*)d_in[0];
    const float* conv_w    = (const float*)d_in[1];
    const float* w_first   = (const float*)d_in[2];
    const float* b_first   = (const float*)d_in[3];
    const float* w_interim = (const float*)d_in[4];
    const float* b_interim = (const float*)d_in[5];
    const float* w_last    = (const float*)d_in[6];
    // d_in[7] (steps) unused: fixed at 16.

    float* out  = (float*)d_out;            // x_final
    float* hist = out + NELEM;              // history

    cudaFuncSetAttribute(nca_step_kernel,
                         cudaFuncAttributeMaxDynamicSharedMemorySize, SMEM_BYTES);

    preswizzle_kernel<<<(102400 + 255) / 256, 256>>>(w_interim, w_first, w_last);

    // history[0] = x
    copy_f4_kernel<<<NELEM / 4 / 256, 256>>>((const float4*)x, (float4*)hist);

    dim3 grid(WW / 16, HH / 8, BB);
    for (int tstep = 1; tstep <= STEPS; tstep++) {
        nca_step_kernel<<<grid, 256, SMEM_BYTES>>>(
            hist + (size_t)(tstep - 1) * NELEM,
            hist + (size_t)tstep * NELEM,
            conv_w, b_first, b_interim);
    }

    // x_final = history[STEPS]
    copy_f4_kernel<<<NELEM / 4 / 256, 256>>>(
        (const float4*)(hist + (size_t)STEPS * NELEM), (float4*)out);
}

// round 10
// speedup vs baseline: 2.2028x; 1.0413x over previous
#include <cuda_runtime.h>
#include <cuda_bf16.h>
#include <cstdint>

// Problem constants
#define BB 8
#define HH 128
#define WW 128
#define CC 16
#define HID 256
#define STEPS 16
#define NELEM (BB*HH*WW*CC)   // 2,097,152

// SMEM layout (32-bit words). CTA tile: 8 y-rows x 16 x-cols = 128 cells (M=128).
#define OFF_HALO 0            // fp32 halo, channel-major: 16ch * 10y * 18x = 2880
#define OFF_CW   2880         // fp32 transposed conv w: [ci*9+rs][16 o] = 2304
#define OFF_P    5184         // P frags (bf16 packed): 8mt * 32lane * 4 u32 = 1024
#define OFF_WFL  6208         // w_first (2048 u32) + w_last (2048 u32) = 4096
#define OFF_ACT  10304        // acts: 8mt * 16ktile * 32lane * 4 u32 = 16384
#define OFF_WBUF 26688        // 4-slot panel ring: 4 * 4096 u32 = 16384
#define SMEM_WORDS 43072
#define SMEM_BYTES (SMEM_WORDS*4)   // 172,288 B

#define NTHREADS 512

// Pre-swizzled bf16-packed weights (u32 = 2 bf16), written once per launch.
// interim: 24 panels (l*8+p) * 4096; u32 idx in panel = ((nt*2+kt)*32+lane)*2+b
//          n = nt*8+(lane>>2), k = p*32 + kt*16 + 2*(lane&3) + 8*b  (pair k,k+1)
#define WU_FIRST 98304
#define WU_LAST  100352
__device__ uint32_t g_wswz[102400];

__device__ __forceinline__ uint32_t packbf(float lo, float hi) {
    uint32_t u;
    asm("cvt.rn.bf16x2.f32 %0, %1, %2;" : "=r"(u) : "f"(hi), "f"(lo));
    return u;
}

__device__ __forceinline__ void mmabf(float* c, const uint4& a, const uint2& b) {
    asm volatile(
        "mma.sync.aligned.m16n8k16.row.col.f32.bf16.bf16.f32 "
        "{%0,%1,%2,%3}, {%4,%5,%6,%7}, {%8,%9}, {%0,%1,%2,%3};\n"
        : "+f"(c[0]), "+f"(c[1]), "+f"(c[2]), "+f"(c[3])
        : "r"(a.x), "r"(a.y), "r"(a.z), "r"(a.w), "r"(b.x), "r"(b.y));
}

__device__ __forceinline__ void cpa16(uint32_t dst, const void* src) {
    asm volatile("cp.async.cg.shared.global [%0], [%1], 16;\n" :: "r"(dst), "l"(src));
}
__device__ __forceinline__ void cpa_commit() { asm volatile("cp.async.commit_group;\n" ::: "memory"); }
__device__ __forceinline__ void cpa_wait2()  { asm volatile("cp.async.wait_group 2;\n"  ::: "memory"); }

// ---------------- Pre-swizzle weights into packed-bf16 mma fragment order -------------
__global__ void preswizzle_kernel(const float* __restrict__ wi,
                                  const float* __restrict__ wf,
                                  const float* __restrict__ wl)
{
    int idx = blockIdx.x * blockDim.x + threadIdx.x;
    if (idx >= 102400) return;
    float f0, f1;
    if (idx < WU_FIRST) {
        // ((((l*8+p)*32+nt)*2+kt)*32+lane)*2 + b
        int lane = (idx >> 1) & 31, kt = (idx >> 6) & 1, nt = (idx >> 7) & 31;
        int p = (idx >> 12) & 7, l = idx >> 15;
        int g = lane >> 2, t = lane & 3;
        int n = nt * 8 + g;
        int k = p * 32 + kt * 16 + 2 * t + 8 * (idx & 1);
        const float* row = wi + (l * HID + n) * HID;
        f0 = row[k]; f1 = row[k + 1];
    } else if (idx < WU_LAST) {
        int j = idx - WU_FIRST;          // (nt*32+lane)*2 + b
        int lane = (j >> 1) & 31, nt = (j >> 6) & 31;
        int g = lane >> 2, t = lane & 3;
        int n = nt * 8 + g;
        int k = 2 * t + 8 * (j & 1);
        f0 = wf[n * CC + k]; f1 = wf[n * CC + k + 1];
    } else {
        int j = idx - WU_LAST;           // ((kap*2+ntl)*32+lane)*2 + b
        int lane = (j >> 1) & 31, ntl = (j >> 6) & 1, kap = (j >> 7) & 15;
        int g = lane >> 2, t = lane & 3;
        int n = ntl * 8 + g;
        int k = kap * 16 + 2 * t + 8 * (j & 1);
        f0 = wl[n * HID + k]; f1 = wl[n * HID + k + 1];
    }
    g_wswz[idx] = packbf(f0, f1);
}

// ------------- Fused NCA step: M=128 cells per CTA, 512 threads / 16 warps ------------
__global__ __launch_bounds__(NTHREADS, 1)
void nca_step_kernel(const float* __restrict__ hin, float* __restrict__ hout,
                     const float* __restrict__ conv_w,
                     const float* __restrict__ b_first,
                     const float* __restrict__ b_interim)
{
    extern __shared__ float sm[];
    float*    smHalo = sm + OFF_HALO;
    float*    smCwT  = sm + OFF_CW;
    uint32_t* smP    = (uint32_t*)(sm + OFF_P);
    uint32_t* smWFL  = (uint32_t*)(sm + OFF_WFL);
    uint32_t* smAct  = (uint32_t*)(sm + OFF_ACT);
    uint32_t* smWbuf = (uint32_t*)(sm + OFF_WBUF);
    const uint32_t smWbuf_u = (uint32_t)__cvta_generic_to_shared(smWbuf);
    const uint32_t smWFL_u  = (uint32_t)__cvta_generic_to_shared(smWFL);

    const int tid  = threadIdx.x;
    const int lane = tid & 31;
    const int wid  = tid >> 5;
    const int g = lane >> 2;
    const int t = lane & 3;
    const int mw = wid & 1;         // warp m-half: 4 m16-tiles (M=128)
    const int nq = wid >> 1;        // warp n-octant: 4 n8-tiles (N=256)

    const int x0 = blockIdx.x * 16;
    const int y0 = blockIdx.y * 8;
    const int b  = blockIdx.z;
    const float* hbase = hin + (size_t)b * HH * WW * CC;

    // ---- Prologue: G0 = panel0 -> slot0 + w_first/w_last; G1 = panel1; G2 = panel2 ----
    #pragma unroll
    for (int i = 0; i < 2; i++)
        cpa16(smWbuf_u + tid * 32 + i * 16, g_wswz + tid * 8 + i * 4);
    #pragma unroll
    for (int i = 0; i < 2; i++)
        cpa16(smWFL_u + tid * 32 + i * 16, g_wswz + WU_FIRST + tid * 8 + i * 4);
    cpa_commit();
    #pragma unroll
    for (int i = 0; i < 2; i++)
        cpa16(smWbuf_u + 4096 * 4 + tid * 32 + i * 16, g_wswz + 4096 + tid * 8 + i * 4);
    cpa_commit();
    #pragma unroll
    for (int i = 0; i < 2; i++)
        cpa16(smWbuf_u + 2 * 4096 * 4 + tid * 32 + i * 16, g_wswz + 2 * 4096 + tid * 8 + i * 4);
    cpa_commit();

    // ---- Halo (fp32, channel-major [c][y 10][x 18], zero padded) + conv weights ----
    for (int f = tid; f < 2880; f += NTHREADS) {
        int xx = f % 18;
        int yy = (f / 18) % 10;
        int c  = f / 180;
        int gx = x0 - 1 + xx;
        int gy = y0 - 1 + yy;
        float v = 0.f;
        if (gy >= 0 && gy < HH && gx >= 0 && gx < WW)
            v = hbase[((size_t)gy * WW + gx) * CC + c];
        smHalo[f] = v;
    }
    for (int f = tid; f < 2304; f += NTHREADS)
        smCwT[f] = conv_w[(f & 15) * 144 + (f >> 4)];
    __syncthreads();

    // ---- Conv 3x3 (fp32): thread = (cell m = tid&127, channel group og = tid>>7) ----
    {
        const int m  = tid & 127;
        const int og = tid >> 7;          // 4 output channels per thread (og 0..3)
        const int ly = m >> 4, lx = m & 15;
        float a4[4] = {0.f, 0.f, 0.f, 0.f};
        #pragma unroll
        for (int ci = 0; ci < 16; ci++) {
            #pragma unroll
            for (int r = 0; r < 3; r++) {
                #pragma unroll
                for (int s = 0; s < 3; s++) {
                    float hv = smHalo[ci * 180 + (ly + s) * 18 + (lx + r)];
                    const float* wp = smCwT + (ci * 9 + r * 3 + s) * 16 + og * 4;
                    float4 w0 = *(const float4*)(wp);
                    a4[0] = fmaf(hv, w0.x, a4[0]); a4[1] = fmaf(hv, w0.y, a4[1]);
                    a4[2] = fmaf(hv, w0.z, a4[2]); a4[3] = fmaf(hv, w0.w, a4[3]);
                }
            }
        }
        // pack P into bf16 A-frag layout (single k16 tile); channels c = og*4 + j
        const int mt = m >> 4;
        const int r  = m & 15;
        const int gp = r & 7, rh = r >> 3;
        #pragma unroll
        for (int j = 0; j < 4; j += 2) {
            uint32_t u = packbf(a4[j], a4[j + 1]);
            int lanep = gp * 4 + (og & 1) * 2 + (j >> 1);   // t = k-pair index
            int slot  = rh + 2 * (og >> 1);                 // k+8 half
            smP[(mt * 32 + lanep) * 4 + slot] = u;
        }
    }
    cpa_wait2();        // G0 done: panel0 + w_first/w_last resident
    __syncthreads();    // P visible

    // ---- First layer: 16 -> 256 via bf16 mma. Warp tile: 64(M) x 32(N). ----
    float acc[4][4][4];
    {
        #pragma unroll
        for (int nt = 0; nt < 4; nt++) {
            int n = nq * 32 + nt * 8 + 2 * t;
            float bz0 = b_first[n];
            float bz1 = b_first[n + 1];
            #pragma unroll
            for (int mtl = 0; mtl < 4; mtl++) {
                acc[mtl][nt][0] = bz0; acc[mtl][nt][1] = bz1;
                acc[mtl][nt][2] = bz0; acc[mtl][nt][3] = bz1;
            }
        }
        uint4 af[4];
        #pragma unroll
        for (int mtl = 0; mtl < 4; mtl++)
            af[mtl] = ((const uint4*)smP)[(mw * 4 + mtl) * 32 + lane];
        #pragma unroll
        for (int nt = 0; nt < 4; nt++) {
            uint2 bch = ((const uint2*)smWFL)[(nq * 4 + nt) * 32 + lane];
            #pragma unroll
            for (int mtl = 0; mtl < 4; mtl++)
                mmabf(acc[mtl][nt], af[mtl], bch);
        }
        // epilogue: relu + pack into smAct (virgin region; no cross-warp hazard)
        #pragma unroll
        for (int mtl = 0; mtl < 4; mtl++) {
            const int mt_g = mw * 4 + mtl;
            #pragma unroll
            for (int nt = 0; nt < 4; nt++) {
                const int kap = nq * 2 + (nt >> 1);
                uint32_t u0 = packbf(fmaxf(acc[mtl][nt][0], 0.f), fmaxf(acc[mtl][nt][1], 0.f));
                uint32_t u1 = packbf(fmaxf(acc[mtl][nt][2], 0.f), fmaxf(acc[mtl][nt][3], 0.f));
                uint32_t* dst = smAct + ((mt_g * 16 + kap) * 32 + lane) * 4 + 2 * (nt & 1);
                *(uint2*)dst = make_uint2(u0, u1);
            }
        }
    }

    // ---- 3 interim layers: 24 k-panels, 4-slot ring prefetched 3 ahead ----
    #pragma unroll 1
    for (int q = 0; q < 24; q++) {
        const int l = q >> 3, p = q & 7;
        cpa_wait2();        // panel q's group complete (2 newer pending)
        __syncthreads();    // panel-q data + (at p==0) prev epilogue visible;
                            // slot (q+3)&3 == (q-1)&3 fully consumed by all warps
        if (q < 21) {
            const uint32_t* src = g_wswz + (size_t)(q + 3) * 4096;
            uint32_t dst = smWbuf_u + ((q + 3) & 3) * (4096 * 4);
            #pragma unroll
            for (int i = 0; i < 2; i++)
                cpa16(dst + tid * 32 + i * 16, src + tid * 8 + i * 4);
        }
        cpa_commit();       // one group per panel (empty for q>=21)

        if (p == 0) {
            #pragma unroll
            for (int nt = 0; nt < 4; nt++) {
                int n = nq * 32 + nt * 8 + 2 * t;
                float bz0 = b_interim[l * HID + n];
                float bz1 = b_interim[l * HID + n + 1];
                #pragma unroll
                for (int mtl = 0; mtl < 4; mtl++) {
                    acc[mtl][nt][0] = bz0; acc[mtl][nt][1] = bz1;
                    acc[mtl][nt][2] = bz0; acc[mtl][nt][3] = bz1;
                }
            }
        }

        const uint32_t* wb = smWbuf + (q & 3) * 4096;
        #pragma unroll
        for (int kt = 0; kt < 2; kt++) {
            uint2 bch[4];
            #pragma unroll
            for (int nt = 0; nt < 4; nt++)
                bch[nt] = ((const uint2*)wb)[(((nq * 4 + nt) * 2 + kt) * 32 + lane)];
            uint4 af[4];
            #pragma unroll
            for (int mtl = 0; mtl < 4; mtl++)
                af[mtl] = ((const uint4*)smAct)[((mw * 4 + mtl) * 16 + (p * 2 + kt)) * 32 + lane];
            #pragma unroll
            for (int mtl = 0; mtl < 4; mtl++)
                #pragma unroll
                for (int nt = 0; nt < 4; nt++)
                    mmabf(acc[mtl][nt], af[mtl], bch[nt]);
        }

        if (p == 7) {
            __syncthreads();   // all warps done READING smAct for this layer
            #pragma unroll
            for (int mtl = 0; mtl < 4; mtl++) {
                const int mt_g = mw * 4 + mtl;
                #pragma unroll
                for (int nt = 0; nt < 4; nt++) {
                    const int kap = nq * 2 + (nt >> 1);
                    uint32_t u0 = packbf(fmaxf(acc[mtl][nt][0], 0.f), fmaxf(acc[mtl][nt][1], 0.f));
                    uint32_t u1 = packbf(fmaxf(acc[mtl][nt][2], 0.f), fmaxf(acc[mtl][nt][3], 0.f));
                    uint32_t* dst = smAct + ((mt_g * 16 + kap) * 32 + lane) * 4 + 2 * (nt & 1);
                    *(uint2*)dst = make_uint2(u0, u1);
                }
            }
        }
    }

    __syncthreads();   // final acts visible

    // ---- Last layer: 256 -> 16 via bf16 mma + residual + store. ----
    // 16 warps: mt = wid&7 (m16 tile), nh = wid>>3 (channel half).
    {
        const int mt = wid & 7;
        const int nh = wid >> 3;
        const uint32_t* wl = smWFL + 2048;
        float acc2[4] = {0.f, 0.f, 0.f, 0.f};
        #pragma unroll 4
        for (int kap = 0; kap < 16; kap++) {
            uint4 a  = ((const uint4*)smAct)[(mt * 16 + kap) * 32 + lane];
            uint2 b0 = ((const uint2*)wl)[(kap * 2 + nh) * 32 + lane];
            mmabf(acc2, a, b0);
        }
        #pragma unroll
        for (int rh = 0; rh < 2; rh++)
            #pragma unroll
            for (int j = 0; j < 2; j++) {
                int ch = nh * 8 + 2 * t + j;
                int m  = mt * 16 + rh * 8 + g;
                int ly = m >> 4, lx = m & 15;
                hout[(((size_t)b * HH + (y0 + ly)) * WW + (x0 + lx)) * CC + ch] =
                    smHalo[ch * 180 + (ly + 1) * 18 + (lx + 1)] + acc2[rh * 2 + j];
            }
    }
}

__global__ void copy_f4_kernel(const float4* __restrict__ src, float4* __restrict__ dst)
{
    int i = blockIdx.x * blockDim.x + threadIdx.x;
    dst[i] = src[i];
}

extern "C" void kernel_launch(void* const* d_in, const int* in_sizes, int n_in,
                              void* d_out, int out_size)
{
    const float* x         = (const float*)d_in[0];
    const float* conv_w    = (const float*)d_in[1];
    const float* w_first   = (const float*)d_in[2];
    const float* b_first   = (const float*)d_in[3];
    const float* w_interim = (const float*)d_in[4];
    const float* b_interim = (const float*)d_in[5];
    const float* w_last    = (const float*)d_in[6];
    // d_in[7] (steps) unused: fixed at 16.

    float* out  = (float*)d_out;            // x_final
    float* hist = out + NELEM;              // history

    cudaFuncSetAttribute(nca_step_kernel,
                         cudaFuncAttributeMaxDynamicSharedMemorySize, SMEM_BYTES);

    preswizzle_kernel<<<(102400 + 255) / 256, 256>>>(w_interim, w_first, w_last);

    // history[0] = x
    copy_f4_kernel<<<NELEM / 4 / 256, 256>>>((const float4*)x, (float4*)hist);

    dim3 grid(WW / 16, HH / 8, BB);
    for (int tstep = 1; tstep <= STEPS; tstep++) {
        nca_step_kernel<<<grid, NTHREADS, SMEM_BYTES>>>(
            hist + (size_t)(tstep - 1) * NELEM,
            hist + (size_t)tstep * NELEM,
            conv_w, b_first, b_interim);
    }

    // x_final = history[STEPS]
    copy_f4_kernel<<<NELEM / 4 / 256, 256>>>(
        (const float4*)(hist + (size_t)STEPS * NELEM), (float4*)out);
}